// round 3
// baseline (speedup 1.0000x reference)
#include <cuda_runtime.h>
#include <cstdint>

#define N_NODES 50000
#define N_EDGES 600000
#define D_IN    128
#define D_HID   1024
#define D_OUT   128

// Scratch (allocation-free rule: __device__ globals).
// NOTE: only ever referenced from DEVICE code — passing these symbols as
// kernel arguments from host code silently passes the host shadow address
// (the bug that zeroed rounds 1-2).
__device__ float g_h[(size_t)N_NODES * D_IN];        // 25.6 MB
__device__ float g_hidden[(size_t)N_NODES * D_HID];  // 204.8 MB

// ---------------------------------------------------------------------------
// Zero the accumulation buffer (float4 stores)
// ---------------------------------------------------------------------------
__global__ void zero_h_kernel() {
    int i = blockIdx.x * blockDim.x + threadIdx.x;
    const int n4 = N_NODES * D_IN / 4;
    if (i < n4) {
        reinterpret_cast<float4*>(g_h)[i] = make_float4(0.f, 0.f, 0.f, 0.f);
    }
}

// ---------------------------------------------------------------------------
// Scatter: one warp per edge. message = feat[src] + edge_feat; atomicAdd into
// g_h[dst] (g_h referenced from device code directly).
// ---------------------------------------------------------------------------
__global__ void scatter_kernel(const float* __restrict__ feat,
                               const float* __restrict__ edge_feat,
                               const int*   __restrict__ src,
                               const int*   __restrict__ dst) {
    int warp = (blockIdx.x * blockDim.x + threadIdx.x) >> 5;
    int lane = threadIdx.x & 31;
    if (warp >= N_EDGES) return;

    int s = src[warp];
    int d = dst[warp];

    const float4 a = reinterpret_cast<const float4*>(feat      + (size_t)s    * D_IN)[lane];
    const float4 b = reinterpret_cast<const float4*>(edge_feat + (size_t)warp * D_IN)[lane];

    float* hp = g_h + (size_t)d * D_IN + lane * 4;
    atomicAdd(hp + 0, a.x + b.x);
    atomicAdd(hp + 1, a.y + b.y);
    atomicAdd(hp + 2, a.z + b.z);
    atomicAdd(hp + 3, a.w + b.w);
}

// ---------------------------------------------------------------------------
// Tiled fp32 SGEMM with fused bias (+ optional ReLU).
// MODE 1: A = g_h      [M,128],  C = g_hidden (ReLU)
// MODE 2: A = g_hidden [M,1024], C = extC (external d_out)
// BM=BN=128, BK=8, 256 threads, 8x8 per thread.
// ---------------------------------------------------------------------------
template <int MODE, bool RELU>
__global__ __launch_bounds__(256, 2)
void gemm_bias_kernel(const float* __restrict__ B,
                      const float* __restrict__ bias,
                      float* __restrict__ extC,
                      int M, int N, int K) {
    const float* A = (MODE == 1) ? g_h : g_hidden;
    float*       C = (MODE == 1) ? g_hidden : extC;

    constexpr int BM = 128, BN = 128, BK = 8, TM = 8, TN = 8;
    __shared__ float As[BK][BM];   // transposed A tile
    __shared__ float Bs[BK][BN];

    const int tid  = threadIdx.x;          // 0..255
    const int row0 = blockIdx.y * BM;
    const int col0 = blockIdx.x * BN;

    const int tr = tid / (BN / TN);        // 0..15
    const int tc = tid % (BN / TN);        // 0..15

    const int a_row = tid / 2;             // 0..127
    const int a_col = (tid & 1) * 4;       // 0 or 4
    const int b_row = tid / 32;            // 0..7
    const int b_col = (tid % 32) * 4;      // 0..124

    float acc[TM][TN];
#pragma unroll
    for (int i = 0; i < TM; i++)
#pragma unroll
        for (int j = 0; j < TN; j++) acc[i][j] = 0.f;

    const int arow_g = row0 + a_row;
    const bool a_ok = (arow_g < M);
    const float* Aptr = A + (size_t)arow_g * K + a_col;
    const float* Bptr = B + (size_t)b_row * N + col0 + b_col;

    for (int k0 = 0; k0 < K; k0 += BK) {
        float4 av = make_float4(0.f, 0.f, 0.f, 0.f);
        if (a_ok) av = *reinterpret_cast<const float4*>(Aptr + k0);
        As[a_col + 0][a_row] = av.x;
        As[a_col + 1][a_row] = av.y;
        As[a_col + 2][a_row] = av.z;
        As[a_col + 3][a_row] = av.w;

        float4 bv = *reinterpret_cast<const float4*>(Bptr + (size_t)k0 * N);
        *reinterpret_cast<float4*>(&Bs[b_row][b_col]) = bv;

        __syncthreads();

#pragma unroll
        for (int k = 0; k < BK; k++) {
            float ra[TM], rb[TN];
#pragma unroll
            for (int i = 0; i < TM; i++) ra[i] = As[k][tr * TM + i];
#pragma unroll
            for (int j = 0; j < TN; j++) rb[j] = Bs[k][tc * TN + j];
#pragma unroll
            for (int i = 0; i < TM; i++)
#pragma unroll
                for (int j = 0; j < TN; j++)
                    acc[i][j] += ra[i] * rb[j];
        }
        __syncthreads();
    }

    float bj[TN];
#pragma unroll
    for (int j = 0; j < TN; j++) bj[j] = bias[col0 + tc * TN + j];

#pragma unroll
    for (int i = 0; i < TM; i++) {
        int r = row0 + tr * TM + i;
        if (r < M) {
            float v[TN];
#pragma unroll
            for (int j = 0; j < TN; j++) {
                float x = acc[i][j] + bj[j];
                if (RELU) x = fmaxf(x, 0.f);
                v[j] = x;
            }
            float* cp = C + (size_t)r * N + col0 + tc * TN;
            *reinterpret_cast<float4*>(cp + 0) = make_float4(v[0], v[1], v[2], v[3]);
            *reinterpret_cast<float4*>(cp + 4) = make_float4(v[4], v[5], v[6], v[7]);
        }
    }
}

// ---------------------------------------------------------------------------
// Launch. Inputs resolved by element count (robust to metadata permutation);
// equal-size pairs (src,dst) and (W1,W2) keep declaration order.
// ---------------------------------------------------------------------------
extern "C" void kernel_launch(void* const* d_in, const int* in_sizes, int n_in,
                              void* d_out, int out_size) {
    const float* feat = nullptr; const float* edge_feat = nullptr;
    const int*   src  = nullptr; const int*   dst = nullptr;
    const float* W1   = nullptr; const float* b1  = nullptr;
    const float* W2   = nullptr; const float* b2  = nullptr;

    for (int i = 0; i < n_in; i++) {
        long long sz = in_sizes[i];
        if      (sz == (long long)N_NODES * D_IN)  feat = (const float*)d_in[i];
        else if (sz == (long long)N_EDGES * D_IN)  edge_feat = (const float*)d_in[i];
        else if (sz == (long long)N_EDGES) { if (!src) src = (const int*)d_in[i]; else dst = (const int*)d_in[i]; }
        else if (sz == (long long)D_IN * D_HID) { // W1 and W2 both 131072
            if (!W1) W1 = (const float*)d_in[i]; else W2 = (const float*)d_in[i];
        }
        else if (sz == (long long)D_HID)           b1 = (const float*)d_in[i];
        else if (sz == (long long)D_OUT)           b2 = (const float*)d_in[i];
    }
    float* out = (float*)d_out;

    // 1) zero accumulator
    {
        int n4 = N_NODES * D_IN / 4;
        zero_h_kernel<<<(n4 + 255) / 256, 256>>>();
    }

    // 2) scatter (one warp per edge, 8 warps per block)
    {
        int blocks = (N_EDGES + 7) / 8;
        scatter_kernel<<<blocks, 256>>>(feat, edge_feat, src, dst);
    }

    // 3) GEMM1: g_hidden = relu(g_h @ W1 + b1)   [50000 x 1024]
    {
        dim3 grid(D_HID / 128, (N_NODES + 127) / 128);
        gemm_bias_kernel<1, true><<<grid, 256>>>(W1, b1, nullptr,
                                                 N_NODES, D_HID, D_IN);
    }

    // 4) GEMM2: out = g_hidden @ W2 + b2         [50000 x 128]
    {
        dim3 grid(D_OUT / 128, (N_NODES + 127) / 128);
        gemm_bias_kernel<2, false><<<grid, 256>>>(W2, b2, out,
                                                  N_NODES, D_OUT, D_HID);
    }
}

// round 5
// speedup vs baseline: 2.2400x; 2.2400x over previous
#include <cuda_runtime.h>
#include <cuda_bf16.h>
#include <cstdint>

#define N_NODES 50000
#define N_EDGES 600000
#define D_IN    128
#define D_HID   1024
#define D_OUT   128

// ---------------------------------------------------------------------------
// Device-global scratch. ONLY referenced from device code (host-shadow bug).
// ---------------------------------------------------------------------------
__device__ float         g_h[(size_t)N_NODES * D_IN];         // fp32 aggregate
__device__ float         g_hidden[(size_t)N_NODES * D_HID];   // fp32 hidden
__device__ __nv_bfloat16 g_w1t_hi[(size_t)D_HID * D_IN];      // W1^T [1024][128]
__device__ __nv_bfloat16 g_w1t_lo[(size_t)D_HID * D_IN];
__device__ __nv_bfloat16 g_w2t_hi[(size_t)D_OUT * D_HID];     // W2^T [128][1024]
__device__ __nv_bfloat16 g_w2t_lo[(size_t)D_OUT * D_HID];

// ---------------------------------------------------------------------------
// Helpers
// ---------------------------------------------------------------------------
__device__ __forceinline__ uint32_t smem_u32(const void* p) {
    uint32_t a;
    asm("{ .reg .u64 t; cvta.to.shared.u64 t, %1; cvt.u32.u64 %0, t; }" : "=r"(a) : "l"(p));
    return a;
}
#define SW128(x) ((x) ^ (((x) >> 3) & 0x70))

__device__ __forceinline__ void ldsm_x4(uint32_t (&r)[4], uint32_t addr) {
    asm volatile("ldmatrix.sync.aligned.m8n8.x4.shared.b16 {%0,%1,%2,%3}, [%4];"
                 : "=r"(r[0]), "=r"(r[1]), "=r"(r[2]), "=r"(r[3]) : "r"(addr));
}
__device__ __forceinline__ void mma_bf16(float (&d)[4], const uint32_t (&a)[4],
                                         uint32_t b0, uint32_t b1) {
    asm volatile(
        "mma.sync.aligned.m16n8k16.row.col.f32.bf16.bf16.f32 "
        "{%0,%1,%2,%3}, {%4,%5,%6,%7}, {%8,%9}, {%0,%1,%2,%3};"
        : "+f"(d[0]), "+f"(d[1]), "+f"(d[2]), "+f"(d[3])
        : "r"(a[0]), "r"(a[1]), "r"(a[2]), "r"(a[3]), "r"(b0), "r"(b1));
}
__device__ __forceinline__ uint32_t pack_bf2(float x0, float x1) {
    __nv_bfloat162 p = __floats2bfloat162_rn(x0, x1);
    return *reinterpret_cast<uint32_t*>(&p);
}

// ---------------------------------------------------------------------------
// Phase 1: zero accumulator
// ---------------------------------------------------------------------------
__global__ void zero_h_kernel() {
    int i = blockIdx.x * blockDim.x + threadIdx.x;
    const int n4 = N_NODES * D_IN / 4;
    if (i < n4) reinterpret_cast<float4*>(g_h)[i] = make_float4(0.f, 0.f, 0.f, 0.f);
}

// ---------------------------------------------------------------------------
// Phase 2: scatter. One warp per edge; float4 vector atomics.
// ---------------------------------------------------------------------------
__global__ void scatter_kernel(const float* __restrict__ feat,
                               const float* __restrict__ edge_feat,
                               const int*   __restrict__ src,
                               const int*   __restrict__ dst) {
    int warp = (blockIdx.x * blockDim.x + threadIdx.x) >> 5;
    int lane = threadIdx.x & 31;
    if (warp >= N_EDGES) return;
    int s = src[warp], d = dst[warp];
    const float4 a = reinterpret_cast<const float4*>(feat      + (size_t)s    * D_IN)[lane];
    const float4 b = reinterpret_cast<const float4*>(edge_feat + (size_t)warp * D_IN)[lane];
    float4 m = make_float4(a.x + b.x, a.y + b.y, a.z + b.z, a.w + b.w);
    atomicAdd(reinterpret_cast<float4*>(g_h + (size_t)d * D_IN + lane * 4), m);
}

// ---------------------------------------------------------------------------
// Phase 3: transpose + split weights into bf16 hi/lo.
// MODE 1: W1[128,1024] -> w1t[1024][128];  MODE 2: W2[1024,128] -> w2t[128][1024]
// ---------------------------------------------------------------------------
template <int MODE>
__global__ void wsplit_kernel(const float* __restrict__ W) {
    constexpr int K = (MODE == 1) ? D_IN : D_HID;
    constexpr int N = (MODE == 1) ? D_HID : D_OUT;
    __nv_bfloat16* out_hi = (MODE == 1) ? g_w1t_hi : g_w2t_hi;
    __nv_bfloat16* out_lo = (MODE == 1) ? g_w1t_lo : g_w2t_lo;
    int i = blockIdx.x * blockDim.x + threadIdx.x;
    if (i < K * N) {
        int k = i / N, n = i % N;
        float x = W[i];
        __nv_bfloat16 hi = __float2bfloat16(x);
        out_hi[(size_t)n * K + k] = hi;
        out_lo[(size_t)n * K + k] = __float2bfloat16(x - __bfloat162float(hi));
    }
}

// ---------------------------------------------------------------------------
// Phase 4/5: bf16 split-GEMM via mma.sync.m16n8k16 (HMMA).
// MODE 1: g_hidden = relu(g_h @ W1 + b1)   (K=128,  N=1024)
// MODE 2: out      = g_hidden @ W2 + b2    (K=1024, N=128)
// A fp32 in gmem -> converted to bf16 hi/lo in loader.
// BM=BN=128, BK=64, 256 thr, warp grid 4(M)x2(N), warp tile 32x64.
// ---------------------------------------------------------------------------
template <int MODE>
__global__ __launch_bounds__(256)
void gemm_mma_kernel(const float* __restrict__ bias, float* __restrict__ extC) {
    constexpr int KDIM = (MODE == 1) ? D_IN : D_HID;
    constexpr int NDIM = (MODE == 1) ? D_HID : D_OUT;
    constexpr int NCH  = KDIM / 64;

    const float* A = (MODE == 1) ? g_h : g_hidden;
    const __nv_bfloat16* Bh = (MODE == 1) ? g_w1t_hi : g_w2t_hi;
    const __nv_bfloat16* Bl = (MODE == 1) ? g_w1t_lo : g_w2t_lo;
    float* C = (MODE == 1) ? g_hidden : extC;

    // dynamic smem: 4 x 16KB tiles (128 rows x 64 bf16, 128B rows, SW128)
    extern __shared__ char smem[];
    const uint32_t sa_hi = smem_u32(smem);
    const uint32_t sa_lo = sa_hi + 16384;
    const uint32_t sb_hi = sa_hi + 32768;
    const uint32_t sb_lo = sa_hi + 49152;

    const int tid  = threadIdx.x;
    const int lane = tid & 31;
    const int wid  = tid >> 5;
    const int wm   = wid >> 1;          // 0..3
    const int wn   = wid & 1;           // 0..1
    const int row0 = blockIdx.y * 128;
    const int col0 = blockIdx.x * 128;

    float acc[2][8][4];
#pragma unroll
    for (int i = 0; i < 2; i++)
#pragma unroll
        for (int j = 0; j < 8; j++)
#pragma unroll
            for (int q = 0; q < 4; q++) acc[i][j][q] = 0.f;

    for (int kc = 0; kc < NCH; kc++) {
        const int k0 = kc * 64;
        // ---- A loader: fp32 -> bf16 hi/lo, 8 floats per iteration ----
#pragma unroll
        for (int c = tid; c < 128 * 8; c += 256) {
            int row = c >> 3, kg = (c & 7) * 8;
            float4 f0 = make_float4(0.f, 0.f, 0.f, 0.f), f1 = f0;
            if (row0 + row < N_NODES) {
                const float* gp = A + (size_t)(row0 + row) * KDIM + k0 + kg;
                f0 = *reinterpret_cast<const float4*>(gp);
                f1 = *reinterpret_cast<const float4*>(gp + 4);
            }
            uint4 vh, vl;
            vh.x = pack_bf2(f0.x, f0.y); vh.y = pack_bf2(f0.z, f0.w);
            vh.z = pack_bf2(f1.x, f1.y); vh.w = pack_bf2(f1.z, f1.w);
            float r0 = f0.x - __bfloat162float(__float2bfloat16(f0.x));
            float r1 = f0.y - __bfloat162float(__float2bfloat16(f0.y));
            float r2 = f0.z - __bfloat162float(__float2bfloat16(f0.z));
            float r3 = f0.w - __bfloat162float(__float2bfloat16(f0.w));
            float r4 = f1.x - __bfloat162float(__float2bfloat16(f1.x));
            float r5 = f1.y - __bfloat162float(__float2bfloat16(f1.y));
            float r6 = f1.z - __bfloat162float(__float2bfloat16(f1.z));
            float r7 = f1.w - __bfloat162float(__float2bfloat16(f1.w));
            vl.x = pack_bf2(r0, r1); vl.y = pack_bf2(r2, r3);
            vl.z = pack_bf2(r4, r5); vl.w = pack_bf2(r6, r7);
            uint32_t o = SW128((uint32_t)(row * 128 + kg * 2));
            *reinterpret_cast<uint4*>(smem + (o))          = vh;            // sa_hi region
            *reinterpret_cast<uint4*>(smem + (16384 + o))  = vl;            // sa_lo region
        }
        // ---- B loader: pre-split bf16, plain copies ----
#pragma unroll
        for (int c = tid; c < 128 * 8; c += 256) {
            int row = c >> 3, kg = (c & 7) * 8;
            size_t g = (size_t)(col0 + row) * KDIM + k0 + kg;
            uint4 vh = *reinterpret_cast<const uint4*>(Bh + g);
            uint4 vl = *reinterpret_cast<const uint4*>(Bl + g);
            uint32_t o = SW128((uint32_t)(row * 128 + kg * 2));
            *reinterpret_cast<uint4*>(smem + (32768 + o)) = vh;
            *reinterpret_cast<uint4*>(smem + (49152 + o)) = vl;
        }
        __syncthreads();

        // ---- 4 k16 steps ----
#pragma unroll
        for (int ks = 0; ks < 4; ks++) {
            const int kb = ks * 32;  // bytes into 128B row
            uint32_t ah[2][4], al[2][4];
#pragma unroll
            for (int mt = 0; mt < 2; mt++) {
                int arow = wm * 32 + mt * 16 + (lane & 15);
                uint32_t off = SW128((uint32_t)(arow * 128 + kb + (lane >> 4) * 16));
                ldsm_x4(ah[mt], sa_hi + off);
                ldsm_x4(al[mt], sa_lo + off);
            }
#pragma unroll
            for (int p = 0; p < 4; p++) {
                int brow = wn * 64 + p * 16 + (lane >> 4) * 8 + (lane & 7);
                uint32_t off = SW128((uint32_t)(brow * 128 + kb + ((lane >> 3) & 1) * 16));
                uint32_t bh[4], bl[4];
                ldsm_x4(bh, sb_hi + off);
                ldsm_x4(bl, sb_lo + off);
#pragma unroll
                for (int mt = 0; mt < 2; mt++) {
                    mma_bf16(acc[mt][2 * p],     ah[mt], bh[0], bh[1]);
                    mma_bf16(acc[mt][2 * p],     ah[mt], bl[0], bl[1]);
                    mma_bf16(acc[mt][2 * p],     al[mt], bh[0], bh[1]);
                    mma_bf16(acc[mt][2 * p + 1], ah[mt], bh[2], bh[3]);
                    mma_bf16(acc[mt][2 * p + 1], ah[mt], bl[2], bl[3]);
                    mma_bf16(acc[mt][2 * p + 1], al[mt], bh[2], bh[3]);
                }
            }
        }
        __syncthreads();
    }

    // ---- epilogue: bias (+ReLU for MODE 1), fp32 stores ----
#pragma unroll
    for (int mt = 0; mt < 2; mt++) {
        int r = row0 + wm * 32 + mt * 16 + (lane >> 2);
#pragma unroll
        for (int nt = 0; nt < 8; nt++) {
            int col = col0 + wn * 64 + nt * 8 + (lane & 3) * 2;
            float bv0 = __ldg(bias + col), bv1 = __ldg(bias + col + 1);
            float x0 = acc[mt][nt][0] + bv0, x1 = acc[mt][nt][1] + bv1;
            float x2 = acc[mt][nt][2] + bv0, x3 = acc[mt][nt][3] + bv1;
            if (MODE == 1) {
                x0 = fmaxf(x0, 0.f); x1 = fmaxf(x1, 0.f);
                x2 = fmaxf(x2, 0.f); x3 = fmaxf(x3, 0.f);
            }
            if (r < N_NODES)
                *reinterpret_cast<float2*>(C + (size_t)r * NDIM + col) = make_float2(x0, x1);
            if (r + 8 < N_NODES)
                *reinterpret_cast<float2*>(C + (size_t)(r + 8) * NDIM + col) = make_float2(x2, x3);
        }
    }
}

// ---------------------------------------------------------------------------
// Launch
// ---------------------------------------------------------------------------
extern "C" void kernel_launch(void* const* d_in, const int* in_sizes, int n_in,
                              void* d_out, int out_size) {
    const float* feat = nullptr; const float* edge_feat = nullptr;
    const int*   src  = nullptr; const int*   dst = nullptr;
    const float* W1   = nullptr; const float* b1  = nullptr;
    const float* W2   = nullptr; const float* b2  = nullptr;

    for (int i = 0; i < n_in; i++) {
        long long sz = in_sizes[i];
        if      (sz == (long long)N_NODES * D_IN)  feat = (const float*)d_in[i];
        else if (sz == (long long)N_EDGES * D_IN)  edge_feat = (const float*)d_in[i];
        else if (sz == (long long)N_EDGES) { if (!src) src = (const int*)d_in[i]; else dst = (const int*)d_in[i]; }
        else if (sz == (long long)D_IN * D_HID) { if (!W1) W1 = (const float*)d_in[i]; else W2 = (const float*)d_in[i]; }
        else if (sz == (long long)D_HID)           b1 = (const float*)d_in[i];
        else if (sz == (long long)D_OUT)           b2 = (const float*)d_in[i];
    }
    float* out = (float*)d_out;

    constexpr int SMEM = 65536;
    cudaFuncSetAttribute(gemm_mma_kernel<1>, cudaFuncAttributeMaxDynamicSharedMemorySize, SMEM);
    cudaFuncSetAttribute(gemm_mma_kernel<2>, cudaFuncAttributeMaxDynamicSharedMemorySize, SMEM);

    // 1) zero accumulator
    { int n4 = N_NODES * D_IN / 4; zero_h_kernel<<<(n4 + 255) / 256, 256>>>(); }
    // 2) scatter
    { int blocks = (N_EDGES + 7) / 8; scatter_kernel<<<blocks, 256>>>(feat, edge_feat, src, dst); }
    // 3) weight transpose+split (tiny)
    { int n = D_IN * D_HID; wsplit_kernel<1><<<(n + 255) / 256, 256>>>(W1); }
    { int n = D_HID * D_OUT; wsplit_kernel<2><<<(n + 255) / 256, 256>>>(W2); }
    // 4) GEMM1: g_hidden = relu(g_h @ W1 + b1)   grid 8 x 391
    {
        dim3 grid(D_HID / 128, (N_NODES + 127) / 128);
        gemm_mma_kernel<1><<<grid, 256, SMEM>>>(b1, nullptr);
    }
    // 5) GEMM2: out = g_hidden @ W2 + b2         grid 1 x 391
    {
        dim3 grid(D_OUT / 128, (N_NODES + 127) / 128);
        gemm_mma_kernel<2><<<grid, 256, SMEM>>>(b2, out);
    }
}

// round 6
// speedup vs baseline: 2.2598x; 1.0088x over previous
#include <cuda_runtime.h>
#include <cuda_bf16.h>
#include <cstdint>

#define N_NODES 50000
#define N_EDGES 600000
#define D_IN    128
#define D_HID   1024
#define D_OUT   128

// ---------------------------------------------------------------------------
// Device-global scratch. ONLY referenced from device code (host-shadow bug).
// ---------------------------------------------------------------------------
__device__ float         g_h[(size_t)N_NODES * D_IN];         // fp32 aggregate
__device__ float         g_hidden[(size_t)N_NODES * D_HID];   // fp32 hidden
__device__ __nv_bfloat16 g_w1t_hi[(size_t)D_HID * D_IN];      // W1^T [1024][128]
__device__ __nv_bfloat16 g_w1t_lo[(size_t)D_HID * D_IN];
__device__ __nv_bfloat16 g_w2t_hi[(size_t)D_OUT * D_HID];     // W2^T [128][1024]
__device__ __nv_bfloat16 g_w2t_lo[(size_t)D_OUT * D_HID];

// ---------------------------------------------------------------------------
// Helpers
// ---------------------------------------------------------------------------
__device__ __forceinline__ uint32_t smem_u32(const void* p) {
    uint32_t a;
    asm("{ .reg .u64 t; cvta.to.shared.u64 t, %1; cvt.u32.u64 %0, t; }" : "=r"(a) : "l"(p));
    return a;
}
#define SW128(x) ((x) ^ (((x) >> 3) & 0x70))

__device__ __forceinline__ void ldsm_x4(uint32_t (&r)[4], uint32_t addr) {
    asm volatile("ldmatrix.sync.aligned.m8n8.x4.shared.b16 {%0,%1,%2,%3}, [%4];"
                 : "=r"(r[0]), "=r"(r[1]), "=r"(r[2]), "=r"(r[3]) : "r"(addr));
}
__device__ __forceinline__ void mma_bf16(float (&d)[4], const uint32_t (&a)[4],
                                         uint32_t b0, uint32_t b1) {
    asm volatile(
        "mma.sync.aligned.m16n8k16.row.col.f32.bf16.bf16.f32 "
        "{%0,%1,%2,%3}, {%4,%5,%6,%7}, {%8,%9}, {%0,%1,%2,%3};"
        : "+f"(d[0]), "+f"(d[1]), "+f"(d[2]), "+f"(d[3])
        : "r"(a[0]), "r"(a[1]), "r"(a[2]), "r"(a[3]), "r"(b0), "r"(b1));
}
__device__ __forceinline__ uint32_t pack_bf2(float x0, float x1) {
    __nv_bfloat162 p = __floats2bfloat162_rn(x0, x1);
    return *reinterpret_cast<uint32_t*>(&p);
}

// ---------------------------------------------------------------------------
// Phase 1: zero accumulator
// ---------------------------------------------------------------------------
__global__ void zero_h_kernel() {
    int i = blockIdx.x * blockDim.x + threadIdx.x;
    const int n4 = N_NODES * D_IN / 4;
    if (i < n4) reinterpret_cast<float4*>(g_h)[i] = make_float4(0.f, 0.f, 0.f, 0.f);
}

// ---------------------------------------------------------------------------
// Phase 2: scatter. One warp per edge; float4 vector atomics.
// ---------------------------------------------------------------------------
__global__ void scatter_kernel(const float* __restrict__ feat,
                               const float* __restrict__ edge_feat,
                               const int*   __restrict__ src,
                               const int*   __restrict__ dst) {
    int warp = (blockIdx.x * blockDim.x + threadIdx.x) >> 5;
    int lane = threadIdx.x & 31;
    if (warp >= N_EDGES) return;
    int s = src[warp], d = dst[warp];
    const float4 a = reinterpret_cast<const float4*>(feat      + (size_t)s    * D_IN)[lane];
    const float4 b = reinterpret_cast<const float4*>(edge_feat + (size_t)warp * D_IN)[lane];
    float4 m = make_float4(a.x + b.x, a.y + b.y, a.z + b.z, a.w + b.w);
    atomicAdd(reinterpret_cast<float4*>(g_h + (size_t)d * D_IN + lane * 4), m);
}

// ---------------------------------------------------------------------------
// Phase 3: transpose + split weights into bf16 hi/lo.
// MODE 1: W1[128,1024] -> w1t[1024][128];  MODE 2: W2[1024,128] -> w2t[128][1024]
// ---------------------------------------------------------------------------
template <int MODE>
__global__ void wsplit_kernel(const float* __restrict__ W) {
    constexpr int K = (MODE == 1) ? D_IN : D_HID;
    constexpr int N = (MODE == 1) ? D_HID : D_OUT;
    __nv_bfloat16* out_hi = (MODE == 1) ? g_w1t_hi : g_w2t_hi;
    __nv_bfloat16* out_lo = (MODE == 1) ? g_w1t_lo : g_w2t_lo;
    int i = blockIdx.x * blockDim.x + threadIdx.x;
    if (i < K * N) {
        int k = i / N, n = i % N;
        float x = W[i];
        __nv_bfloat16 hi = __float2bfloat16(x);
        out_hi[(size_t)n * K + k] = hi;
        out_lo[(size_t)n * K + k] = __float2bfloat16(x - __bfloat162float(hi));
    }
}

// ---------------------------------------------------------------------------
// Phase 4/5: bf16 split-GEMM via mma.sync.m16n8k16 (HMMA).
// MODE 1: g_hidden = relu(g_h @ W1 + b1)   (K=128,  N=1024)
// MODE 2: out      = g_hidden @ W2 + b2    (K=1024, N=128)
// A fp32 in gmem -> converted to bf16 hi/lo in loader.
// BM=BN=128, BK=64, 256 thr, warp grid 4(M)x2(N), warp tile 32x64.
// ---------------------------------------------------------------------------
template <int MODE>
__global__ __launch_bounds__(256)
void gemm_mma_kernel(const float* __restrict__ bias, float* __restrict__ extC) {
    constexpr int KDIM = (MODE == 1) ? D_IN : D_HID;
    constexpr int NDIM = (MODE == 1) ? D_HID : D_OUT;
    constexpr int NCH  = KDIM / 64;

    const float* A = (MODE == 1) ? g_h : g_hidden;
    const __nv_bfloat16* Bh = (MODE == 1) ? g_w1t_hi : g_w2t_hi;
    const __nv_bfloat16* Bl = (MODE == 1) ? g_w1t_lo : g_w2t_lo;
    float* C = (MODE == 1) ? g_hidden : extC;

    // dynamic smem: 4 x 16KB tiles (128 rows x 64 bf16, 128B rows, SW128)
    extern __shared__ char smem[];
    const uint32_t sa_hi = smem_u32(smem);
    const uint32_t sa_lo = sa_hi + 16384;
    const uint32_t sb_hi = sa_hi + 32768;
    const uint32_t sb_lo = sa_hi + 49152;

    const int tid  = threadIdx.x;
    const int lane = tid & 31;
    const int wid  = tid >> 5;
    const int wm   = wid >> 1;          // 0..3
    const int wn   = wid & 1;           // 0..1
    const int row0 = blockIdx.y * 128;
    const int col0 = blockIdx.x * 128;

    float acc[2][8][4];
#pragma unroll
    for (int i = 0; i < 2; i++)
#pragma unroll
        for (int j = 0; j < 8; j++)
#pragma unroll
            for (int q = 0; q < 4; q++) acc[i][j][q] = 0.f;

    for (int kc = 0; kc < NCH; kc++) {
        const int k0 = kc * 64;
        // ---- A loader: fp32 -> bf16 hi/lo, 8 floats per iteration ----
#pragma unroll
        for (int c = tid; c < 128 * 8; c += 256) {
            int row = c >> 3, kg = (c & 7) * 8;
            float4 f0 = make_float4(0.f, 0.f, 0.f, 0.f), f1 = f0;
            if (row0 + row < N_NODES) {
                const float* gp = A + (size_t)(row0 + row) * KDIM + k0 + kg;
                f0 = *reinterpret_cast<const float4*>(gp);
                f1 = *reinterpret_cast<const float4*>(gp + 4);
            }
            uint4 vh, vl;
            vh.x = pack_bf2(f0.x, f0.y); vh.y = pack_bf2(f0.z, f0.w);
            vh.z = pack_bf2(f1.x, f1.y); vh.w = pack_bf2(f1.z, f1.w);
            float r0 = f0.x - __bfloat162float(__float2bfloat16(f0.x));
            float r1 = f0.y - __bfloat162float(__float2bfloat16(f0.y));
            float r2 = f0.z - __bfloat162float(__float2bfloat16(f0.z));
            float r3 = f0.w - __bfloat162float(__float2bfloat16(f0.w));
            float r4 = f1.x - __bfloat162float(__float2bfloat16(f1.x));
            float r5 = f1.y - __bfloat162float(__float2bfloat16(f1.y));
            float r6 = f1.z - __bfloat162float(__float2bfloat16(f1.z));
            float r7 = f1.w - __bfloat162float(__float2bfloat16(f1.w));
            vl.x = pack_bf2(r0, r1); vl.y = pack_bf2(r2, r3);
            vl.z = pack_bf2(r4, r5); vl.w = pack_bf2(r6, r7);
            uint32_t o = SW128((uint32_t)(row * 128 + kg * 2));
            *reinterpret_cast<uint4*>(smem + (o))          = vh;            // sa_hi region
            *reinterpret_cast<uint4*>(smem + (16384 + o))  = vl;            // sa_lo region
        }
        // ---- B loader: pre-split bf16, plain copies ----
#pragma unroll
        for (int c = tid; c < 128 * 8; c += 256) {
            int row = c >> 3, kg = (c & 7) * 8;
            size_t g = (size_t)(col0 + row) * KDIM + k0 + kg;
            uint4 vh = *reinterpret_cast<const uint4*>(Bh + g);
            uint4 vl = *reinterpret_cast<const uint4*>(Bl + g);
            uint32_t o = SW128((uint32_t)(row * 128 + kg * 2));
            *reinterpret_cast<uint4*>(smem + (32768 + o)) = vh;
            *reinterpret_cast<uint4*>(smem + (49152 + o)) = vl;
        }
        __syncthreads();

        // ---- 4 k16 steps ----
#pragma unroll
        for (int ks = 0; ks < 4; ks++) {
            const int kb = ks * 32;  // bytes into 128B row
            uint32_t ah[2][4], al[2][4];
#pragma unroll
            for (int mt = 0; mt < 2; mt++) {
                int arow = wm * 32 + mt * 16 + (lane & 15);
                uint32_t off = SW128((uint32_t)(arow * 128 + kb + (lane >> 4) * 16));
                ldsm_x4(ah[mt], sa_hi + off);
                ldsm_x4(al[mt], sa_lo + off);
            }
#pragma unroll
            for (int p = 0; p < 4; p++) {
                int brow = wn * 64 + p * 16 + (lane >> 4) * 8 + (lane & 7);
                uint32_t off = SW128((uint32_t)(brow * 128 + kb + ((lane >> 3) & 1) * 16));
                uint32_t bh[4], bl[4];
                ldsm_x4(bh, sb_hi + off);
                ldsm_x4(bl, sb_lo + off);
#pragma unroll
                for (int mt = 0; mt < 2; mt++) {
                    mma_bf16(acc[mt][2 * p],     ah[mt], bh[0], bh[1]);
                    mma_bf16(acc[mt][2 * p],     ah[mt], bl[0], bl[1]);
                    mma_bf16(acc[mt][2 * p],     al[mt], bh[0], bh[1]);
                    mma_bf16(acc[mt][2 * p + 1], ah[mt], bh[2], bh[3]);
                    mma_bf16(acc[mt][2 * p + 1], ah[mt], bl[2], bl[3]);
                    mma_bf16(acc[mt][2 * p + 1], al[mt], bh[2], bh[3]);
                }
            }
        }
        __syncthreads();
    }

    // ---- epilogue: bias (+ReLU for MODE 1), fp32 stores ----
#pragma unroll
    for (int mt = 0; mt < 2; mt++) {
        int r = row0 + wm * 32 + mt * 16 + (lane >> 2);
#pragma unroll
        for (int nt = 0; nt < 8; nt++) {
            int col = col0 + wn * 64 + nt * 8 + (lane & 3) * 2;
            float bv0 = __ldg(bias + col), bv1 = __ldg(bias + col + 1);
            float x0 = acc[mt][nt][0] + bv0, x1 = acc[mt][nt][1] + bv1;
            float x2 = acc[mt][nt][2] + bv0, x3 = acc[mt][nt][3] + bv1;
            if (MODE == 1) {
                x0 = fmaxf(x0, 0.f); x1 = fmaxf(x1, 0.f);
                x2 = fmaxf(x2, 0.f); x3 = fmaxf(x3, 0.f);
            }
            if (r < N_NODES)
                *reinterpret_cast<float2*>(C + (size_t)r * NDIM + col) = make_float2(x0, x1);
            if (r + 8 < N_NODES)
                *reinterpret_cast<float2*>(C + (size_t)(r + 8) * NDIM + col) = make_float2(x2, x3);
        }
    }
}

// ---------------------------------------------------------------------------
// Launch
// ---------------------------------------------------------------------------
extern "C" void kernel_launch(void* const* d_in, const int* in_sizes, int n_in,
                              void* d_out, int out_size) {
    const float* feat = nullptr; const float* edge_feat = nullptr;
    const int*   src  = nullptr; const int*   dst = nullptr;
    const float* W1   = nullptr; const float* b1  = nullptr;
    const float* W2   = nullptr; const float* b2  = nullptr;

    for (int i = 0; i < n_in; i++) {
        long long sz = in_sizes[i];
        if      (sz == (long long)N_NODES * D_IN)  feat = (const float*)d_in[i];
        else if (sz == (long long)N_EDGES * D_IN)  edge_feat = (const float*)d_in[i];
        else if (sz == (long long)N_EDGES) { if (!src) src = (const int*)d_in[i]; else dst = (const int*)d_in[i]; }
        else if (sz == (long long)D_IN * D_HID) { if (!W1) W1 = (const float*)d_in[i]; else W2 = (const float*)d_in[i]; }
        else if (sz == (long long)D_HID)           b1 = (const float*)d_in[i];
        else if (sz == (long long)D_OUT)           b2 = (const float*)d_in[i];
    }
    float* out = (float*)d_out;

    constexpr int SMEM = 65536;
    cudaFuncSetAttribute(gemm_mma_kernel<1>, cudaFuncAttributeMaxDynamicSharedMemorySize, SMEM);
    cudaFuncSetAttribute(gemm_mma_kernel<2>, cudaFuncAttributeMaxDynamicSharedMemorySize, SMEM);

    // 1) zero accumulator
    { int n4 = N_NODES * D_IN / 4; zero_h_kernel<<<(n4 + 255) / 256, 256>>>(); }
    // 2) scatter
    { int blocks = (N_EDGES + 7) / 8; scatter_kernel<<<blocks, 256>>>(feat, edge_feat, src, dst); }
    // 3) weight transpose+split (tiny)
    { int n = D_IN * D_HID; wsplit_kernel<1><<<(n + 255) / 256, 256>>>(W1); }
    { int n = D_HID * D_OUT; wsplit_kernel<2><<<(n + 255) / 256, 256>>>(W2); }
    // 4) GEMM1: g_hidden = relu(g_h @ W1 + b1)   grid 8 x 391
    {
        dim3 grid(D_HID / 128, (N_NODES + 127) / 128);
        gemm_mma_kernel<1><<<grid, 256, SMEM>>>(b1, nullptr);
    }
    // 5) GEMM2: out = g_hidden @ W2 + b2         grid 1 x 391
    {
        dim3 grid(D_OUT / 128, (N_NODES + 127) / 128);
        gemm_mma_kernel<2><<<grid, 256, SMEM>>>(b2, out);
    }
}

// round 7
// speedup vs baseline: 2.8889x; 1.2784x over previous
#include <cuda_runtime.h>
#include <cuda_bf16.h>
#include <cstdint>

#define N_NODES 50000
#define N_EDGES 600000
#define D_IN    128
#define D_HID   1024
#define D_OUT   128

// ---------------------------------------------------------------------------
// Device-global scratch. ONLY referenced from device code (host-shadow bug).
// (g_hidden eliminated by MLP fusion.)
// ---------------------------------------------------------------------------
__device__ float         g_h[(size_t)N_NODES * D_IN];         // fp32 aggregate
__device__ __nv_bfloat16 g_w1t_hi[(size_t)D_HID * D_IN];      // W1^T [1024][128]
__device__ __nv_bfloat16 g_w1t_lo[(size_t)D_HID * D_IN];
__device__ __nv_bfloat16 g_w2t_hi[(size_t)D_OUT * D_HID];     // W2^T [128][1024]
__device__ __nv_bfloat16 g_w2t_lo[(size_t)D_OUT * D_HID];

// ---------------------------------------------------------------------------
// Helpers
// ---------------------------------------------------------------------------
__device__ __forceinline__ uint32_t smem_u32(const void* p) {
    uint32_t a;
    asm("{ .reg .u64 t; cvta.to.shared.u64 t, %1; cvt.u32.u64 %0, t; }" : "=r"(a) : "l"(p));
    return a;
}
#define SW128(x) ((x) ^ (((x) >> 3) & 0x70))

// 128-row x 128-bf16-k tile stored as two sequential 16KB sub-tiles
// (k-bytes [0,128) and [128,256)), each 128B/row SW128-swizzled.
__device__ __forceinline__ uint32_t toff(int row, int kbyte) {
    uint32_t w = (uint32_t)(row * 128 + (kbyte & 127));
    return (uint32_t)((kbyte >> 7) * 16384) + SW128(w);
}

__device__ __forceinline__ void ldsm_x4(uint32_t (&r)[4], uint32_t addr) {
    asm volatile("ldmatrix.sync.aligned.m8n8.x4.shared.b16 {%0,%1,%2,%3}, [%4];"
                 : "=r"(r[0]), "=r"(r[1]), "=r"(r[2]), "=r"(r[3]) : "r"(addr));
}
__device__ __forceinline__ void mma_bf16(float (&d)[4], const uint32_t (&a)[4],
                                         uint32_t b0, uint32_t b1) {
    asm volatile(
        "mma.sync.aligned.m16n8k16.row.col.f32.bf16.bf16.f32 "
        "{%0,%1,%2,%3}, {%4,%5,%6,%7}, {%8,%9}, {%0,%1,%2,%3};"
        : "+f"(d[0]), "+f"(d[1]), "+f"(d[2]), "+f"(d[3])
        : "r"(a[0]), "r"(a[1]), "r"(a[2]), "r"(a[3]), "r"(b0), "r"(b1));
}
__device__ __forceinline__ uint32_t pack_bf2(float x0, float x1) {
    __nv_bfloat162 p = __floats2bfloat162_rn(x0, x1);
    return *reinterpret_cast<uint32_t*>(&p);
}

// 128x128x128 3-term split MMA: acc += Ahi*Bhi + Ahi*Blo + Alo*Bhi
// Warp grid 4(M)x2(N), warp tile 32x64. Identical frag mapping to R6 (validated).
__device__ __forceinline__ void mma_tile_128(uint32_t a_hi, uint32_t a_lo,
                                             uint32_t b_hi, uint32_t b_lo,
                                             float (&acc)[2][8][4],
                                             int lane, int wm, int wn) {
#pragma unroll
    for (int ks = 0; ks < 8; ks++) {
        const int kb = ks * 32;
        uint32_t ah[2][4], al[2][4];
#pragma unroll
        for (int mt = 0; mt < 2; mt++) {
            int arow = wm * 32 + mt * 16 + (lane & 15);
            uint32_t off = toff(arow, kb + (lane >> 4) * 16);
            ldsm_x4(ah[mt], a_hi + off);
            ldsm_x4(al[mt], a_lo + off);
        }
#pragma unroll
        for (int p = 0; p < 4; p++) {
            int brow = wn * 64 + p * 16 + (lane >> 4) * 8 + (lane & 7);
            uint32_t off = toff(brow, kb + ((lane >> 3) & 1) * 16);
            uint32_t bh[4], bl[4];
            ldsm_x4(bh, b_hi + off);
            ldsm_x4(bl, b_lo + off);
#pragma unroll
            for (int mt = 0; mt < 2; mt++) {
                mma_bf16(acc[mt][2 * p],     ah[mt], bh[0], bh[1]);
                mma_bf16(acc[mt][2 * p],     ah[mt], bl[0], bl[1]);
                mma_bf16(acc[mt][2 * p],     al[mt], bh[0], bh[1]);
                mma_bf16(acc[mt][2 * p + 1], ah[mt], bh[2], bh[3]);
                mma_bf16(acc[mt][2 * p + 1], ah[mt], bl[2], bl[3]);
                mma_bf16(acc[mt][2 * p + 1], al[mt], bh[2], bh[3]);
            }
        }
    }
}

// ---------------------------------------------------------------------------
// Phase 1: zero accumulator
// ---------------------------------------------------------------------------
__global__ void zero_h_kernel() {
    int i = blockIdx.x * blockDim.x + threadIdx.x;
    const int n4 = N_NODES * D_IN / 4;
    if (i < n4) reinterpret_cast<float4*>(g_h)[i] = make_float4(0.f, 0.f, 0.f, 0.f);
}

// ---------------------------------------------------------------------------
// Phase 2: scatter. One warp per edge; float4 vector atomics.
// ---------------------------------------------------------------------------
__global__ void scatter_kernel(const float* __restrict__ feat,
                               const float* __restrict__ edge_feat,
                               const int*   __restrict__ src,
                               const int*   __restrict__ dst) {
    int warp = (blockIdx.x * blockDim.x + threadIdx.x) >> 5;
    int lane = threadIdx.x & 31;
    if (warp >= N_EDGES) return;
    int s = src[warp], d = dst[warp];
    const float4 a = reinterpret_cast<const float4*>(feat      + (size_t)s    * D_IN)[lane];
    const float4 b = reinterpret_cast<const float4*>(edge_feat + (size_t)warp * D_IN)[lane];
    float4 m = make_float4(a.x + b.x, a.y + b.y, a.z + b.z, a.w + b.w);
    atomicAdd(reinterpret_cast<float4*>(g_h + (size_t)d * D_IN + lane * 4), m);
}

// ---------------------------------------------------------------------------
// Phase 3: transpose + split weights into bf16 hi/lo.
// ---------------------------------------------------------------------------
template <int MODE>
__global__ void wsplit_kernel(const float* __restrict__ W) {
    constexpr int K = (MODE == 1) ? D_IN : D_HID;
    constexpr int N = (MODE == 1) ? D_HID : D_OUT;
    __nv_bfloat16* out_hi = (MODE == 1) ? g_w1t_hi : g_w2t_hi;
    __nv_bfloat16* out_lo = (MODE == 1) ? g_w1t_lo : g_w2t_lo;
    int i = blockIdx.x * blockDim.x + threadIdx.x;
    if (i < K * N) {
        int k = i / N, n = i % N;
        float x = W[i];
        __nv_bfloat16 hi = __float2bfloat16(x);
        out_hi[(size_t)n * K + k] = hi;
        out_lo[(size_t)n * K + k] = __float2bfloat16(x - __bfloat162float(hi));
    }
}

// ---------------------------------------------------------------------------
// Phase 4: FUSED MLP. Each CTA: 128 node rows through both layers.
//   A (h tile, K=128) loaded once. For each of 8 hidden chunks:
//     stage1: htile = A @ W1c          (3-term split HMMA)
//     bias+relu+split htile -> smem H (bf16 hi/lo)
//     stage2: oacc += H @ W2c          (3-term split HMMA)
//   hidden never touches DRAM.
// Smem: A(64K) + B(64K, W1c/W2c alternate) + H(64K) = 192KB, 1 CTA/SM.
// ---------------------------------------------------------------------------
__global__ __launch_bounds__(256)
void fused_mlp_kernel(const float* __restrict__ b1, const float* __restrict__ b2,
                      float* __restrict__ out) {
    constexpr int OFF_A_HI = 0,       OFF_A_LO = 32768;
    constexpr int OFF_B_HI = 65536,   OFF_B_LO = 98304;
    constexpr int OFF_H_HI = 131072,  OFF_H_LO = 163840;

    extern __shared__ char smem[];
    const uint32_t sb = smem_u32(smem);
    const int tid = threadIdx.x;
    const int lane = tid & 31;
    const int wid  = tid >> 5;
    const int wm   = wid >> 1;   // 0..3
    const int wn   = wid & 1;    // 0..1
    const int row0 = blockIdx.x * 128;

    // ---- load A = h rows [row0, row0+128), fp32 -> bf16 hi/lo ----
    for (int c = tid; c < 128 * 16; c += 256) {
        int row = c >> 4, ch = c & 15;               // ch: 16B chunk = 8 values
        float4 f0 = make_float4(0.f, 0.f, 0.f, 0.f), f1 = f0;
        if (row0 + row < N_NODES) {
            const float* gp = g_h + (size_t)(row0 + row) * D_IN + ch * 8;
            f0 = *reinterpret_cast<const float4*>(gp);
            f1 = *reinterpret_cast<const float4*>(gp + 4);
        }
        uint4 vh, vl;
        vh.x = pack_bf2(f0.x, f0.y); vh.y = pack_bf2(f0.z, f0.w);
        vh.z = pack_bf2(f1.x, f1.y); vh.w = pack_bf2(f1.z, f1.w);
        float r0 = f0.x - __bfloat162float(__float2bfloat16(f0.x));
        float r1 = f0.y - __bfloat162float(__float2bfloat16(f0.y));
        float r2 = f0.z - __bfloat162float(__float2bfloat16(f0.z));
        float r3 = f0.w - __bfloat162float(__float2bfloat16(f0.w));
        float r4 = f1.x - __bfloat162float(__float2bfloat16(f1.x));
        float r5 = f1.y - __bfloat162float(__float2bfloat16(f1.y));
        float r6 = f1.z - __bfloat162float(__float2bfloat16(f1.z));
        float r7 = f1.w - __bfloat162float(__float2bfloat16(f1.w));
        vl.x = pack_bf2(r0, r1); vl.y = pack_bf2(r2, r3);
        vl.z = pack_bf2(r4, r5); vl.w = pack_bf2(r6, r7);
        uint32_t o = toff(row, ch * 16);
        *reinterpret_cast<uint4*>(smem + OFF_A_HI + o) = vh;
        *reinterpret_cast<uint4*>(smem + OFF_A_LO + o) = vl;
    }

    float oacc[2][8][4];
#pragma unroll
    for (int i = 0; i < 2; i++)
#pragma unroll
        for (int j = 0; j < 8; j++)
#pragma unroll
            for (int q = 0; q < 4; q++) oacc[i][j][q] = 0.f;

    for (int c8 = 0; c8 < 8; c8++) {
        // ---- load W1 chunk [c8*128 .. +128)[0..128) bf16 hi/lo -> B ----
        for (int c = tid; c < 128 * 16; c += 256) {
            int n = c >> 4, ch = c & 15;
            size_t g = (size_t)(c8 * 128 + n) * D_IN + ch * 8;
            uint4 vh = *reinterpret_cast<const uint4*>(g_w1t_hi + g);
            uint4 vl = *reinterpret_cast<const uint4*>(g_w1t_lo + g);
            uint32_t o = toff(n, ch * 16);
            *reinterpret_cast<uint4*>(smem + OFF_B_HI + o) = vh;
            *reinterpret_cast<uint4*>(smem + OFF_B_LO + o) = vl;
        }
        __syncthreads();   // A + W1c visible; prev-chunk stage2 ldsm done (loop-end sync)

        // ---- stage 1: htile = A @ W1c ----
        float hacc[2][8][4];
#pragma unroll
        for (int i = 0; i < 2; i++)
#pragma unroll
            for (int j = 0; j < 8; j++)
#pragma unroll
                for (int q = 0; q < 4; q++) hacc[i][j][q] = 0.f;
        mma_tile_128(sb + OFF_A_HI, sb + OFF_A_LO, sb + OFF_B_HI, sb + OFF_B_LO,
                     hacc, lane, wm, wn);
        __syncthreads();   // all warps done reading B (W1c) before overwrite

        // ---- bias + relu + split -> H (each thread owns 2x8x(2+2) elems) ----
#pragma unroll
        for (int mt = 0; mt < 2; mt++) {
            int r = wm * 32 + mt * 16 + (lane >> 2);
#pragma unroll
            for (int nt = 0; nt < 8; nt++) {
                int cl = wn * 64 + nt * 8 + (lane & 3) * 2;
                float bv0 = __ldg(b1 + c8 * 128 + cl);
                float bv1 = __ldg(b1 + c8 * 128 + cl + 1);
                float x0 = fmaxf(hacc[mt][nt][0] + bv0, 0.f);
                float x1 = fmaxf(hacc[mt][nt][1] + bv1, 0.f);
                float x2 = fmaxf(hacc[mt][nt][2] + bv0, 0.f);
                float x3 = fmaxf(hacc[mt][nt][3] + bv1, 0.f);
                uint32_t h01 = pack_bf2(x0, x1);
                uint32_t h23 = pack_bf2(x2, x3);
                uint32_t l01 = pack_bf2(x0 - __bfloat162float(__float2bfloat16(x0)),
                                        x1 - __bfloat162float(__float2bfloat16(x1)));
                uint32_t l23 = pack_bf2(x2 - __bfloat162float(__float2bfloat16(x2)),
                                        x3 - __bfloat162float(__float2bfloat16(x3)));
                uint32_t o0 = toff(r,     cl * 2);
                uint32_t o1 = toff(r + 8, cl * 2);
                *reinterpret_cast<uint32_t*>(smem + OFF_H_HI + o0) = h01;
                *reinterpret_cast<uint32_t*>(smem + OFF_H_LO + o0) = l01;
                *reinterpret_cast<uint32_t*>(smem + OFF_H_HI + o1) = h23;
                *reinterpret_cast<uint32_t*>(smem + OFF_H_LO + o1) = l23;
            }
        }

        // ---- load W2 chunk [n=0..128)[c8*128 .. +128) -> B (reused) ----
        for (int c = tid; c < 128 * 16; c += 256) {
            int n = c >> 4, ch = c & 15;
            size_t g = (size_t)n * D_HID + c8 * 128 + ch * 8;
            uint4 vh = *reinterpret_cast<const uint4*>(g_w2t_hi + g);
            uint4 vl = *reinterpret_cast<const uint4*>(g_w2t_lo + g);
            uint32_t o = toff(n, ch * 16);
            *reinterpret_cast<uint4*>(smem + OFF_B_HI + o) = vh;
            *reinterpret_cast<uint4*>(smem + OFF_B_LO + o) = vl;
        }
        __syncthreads();   // H + W2c visible

        // ---- stage 2: oacc += H @ W2c ----
        mma_tile_128(sb + OFF_H_HI, sb + OFF_H_LO, sb + OFF_B_HI, sb + OFF_B_LO,
                     oacc, lane, wm, wn);
        __syncthreads();   // stage2 ldsm done before next chunk overwrites B/H
    }

    // ---- final epilogue: out = oacc + b2 ----
#pragma unroll
    for (int mt = 0; mt < 2; mt++) {
        int r = row0 + wm * 32 + mt * 16 + (lane >> 2);
#pragma unroll
        for (int nt = 0; nt < 8; nt++) {
            int col = wn * 64 + nt * 8 + (lane & 3) * 2;
            float bv0 = __ldg(b2 + col), bv1 = __ldg(b2 + col + 1);
            if (r < N_NODES)
                *reinterpret_cast<float2*>(out + (size_t)r * D_OUT + col) =
                    make_float2(oacc[mt][nt][0] + bv0, oacc[mt][nt][1] + bv1);
            if (r + 8 < N_NODES)
                *reinterpret_cast<float2*>(out + (size_t)(r + 8) * D_OUT + col) =
                    make_float2(oacc[mt][nt][2] + bv0, oacc[mt][nt][3] + bv1);
        }
    }
}

// ---------------------------------------------------------------------------
// Launch
// ---------------------------------------------------------------------------
extern "C" void kernel_launch(void* const* d_in, const int* in_sizes, int n_in,
                              void* d_out, int out_size) {
    const float* feat = nullptr; const float* edge_feat = nullptr;
    const int*   src  = nullptr; const int*   dst = nullptr;
    const float* W1   = nullptr; const float* b1  = nullptr;
    const float* W2   = nullptr; const float* b2  = nullptr;

    for (int i = 0; i < n_in; i++) {
        long long sz = in_sizes[i];
        if      (sz == (long long)N_NODES * D_IN)  feat = (const float*)d_in[i];
        else if (sz == (long long)N_EDGES * D_IN)  edge_feat = (const float*)d_in[i];
        else if (sz == (long long)N_EDGES) { if (!src) src = (const int*)d_in[i]; else dst = (const int*)d_in[i]; }
        else if (sz == (long long)D_IN * D_HID) { if (!W1) W1 = (const float*)d_in[i]; else W2 = (const float*)d_in[i]; }
        else if (sz == (long long)D_HID)           b1 = (const float*)d_in[i];
        else if (sz == (long long)D_OUT)           b2 = (const float*)d_in[i];
    }
    float* out = (float*)d_out;

    constexpr int SMEM = 196608;   // 192KB
    cudaFuncSetAttribute(fused_mlp_kernel, cudaFuncAttributeMaxDynamicSharedMemorySize, SMEM);

    // 1) zero accumulator
    { int n4 = N_NODES * D_IN / 4; zero_h_kernel<<<(n4 + 255) / 256, 256>>>(); }
    // 2) scatter
    { int blocks = (N_EDGES + 7) / 8; scatter_kernel<<<blocks, 256>>>(feat, edge_feat, src, dst); }
    // 3) weight transpose+split (tiny)
    { int n = D_IN * D_HID; wsplit_kernel<1><<<(n + 255) / 256, 256>>>(W1); }
    { int n = D_HID * D_OUT; wsplit_kernel<2><<<(n + 255) / 256, 256>>>(W2); }
    // 4) fused MLP: out = relu(h@W1+b1)@W2 + b2
    {
        dim3 grid((N_NODES + 127) / 128);
        fused_mlp_kernel<<<grid, 256, SMEM>>>(b1, b2, out);
    }
}